// round 14
// baseline (speedup 1.0000x reference)
#include <cuda_runtime.h>
#include <cuda_bf16.h>
#include <cuda_fp16.h>
#include <cstdint>

#define N_NODES 20000
#define N_EDGES 1280000
#define HD 64
#define NLAYERS 4
#define NTILE16 (N_EDGES / 16)   // 80000 warp-tiles of 16 edges

// ---------------- device scratch (no cudaMalloc allowed) ----------------
__device__ float g_h[N_NODES * HD];
__device__ float g_A[N_NODES * HD];
__device__ float g_B[N_NODES * HD];
__device__ float g_P[N_NODES * HD];
__device__ float g_vg[N_NODES];
__device__ float g_coord[2][N_NODES * 3];
__device__ float g_vel[N_NODES * 3];
__device__ __half g_ef16[(size_t)N_EDGES * HD];   // per-edge features, fp16
__device__ float g_trans[N_EDGES * 3];
__device__ int   g_cnt[N_NODES];
__device__ int   g_off[N_NODES + 1];
__device__ int   g_cur[N_NODES];
__device__ int   g_eid[N_EDGES];
__device__ float g_inv[N_NODES];

__device__ __forceinline__ float siluf(float x) {
    return __fdividef(x, 1.0f + __expf(-x));
}
__device__ __forceinline__ uint32_t smem_u32(const void* p) {
    uint32_t a;
    asm("{ .reg .u64 t; cvta.to.shared.u64 t, %1; cvt.u32.u64 %0, t; }"
        : "=r"(a) : "l"(p));
    return a;
}
__device__ __forceinline__ uint32_t pk_bf2(float a, float b) {
    __nv_bfloat162 t = __floats2bfloat162_rn(a, b);
    return reinterpret_cast<uint32_t&>(t);
}
__device__ __forceinline__ float bf_hi(float v) {
    return __bfloat162float(__float2bfloat16(v));
}

#define LDSM4(r, a) \
    asm volatile("ldmatrix.sync.aligned.m8n8.x4.shared.b16 {%0,%1,%2,%3}, [%4];" \
        : "=r"((r)[0]), "=r"((r)[1]), "=r"((r)[2]), "=r"((r)[3]) : "r"(a))
#define LDSM4T(r, a) \
    asm volatile("ldmatrix.sync.aligned.m8n8.x4.trans.shared.b16 {%0,%1,%2,%3}, [%4];" \
        : "=r"((r)[0]), "=r"((r)[1]), "=r"((r)[2]), "=r"((r)[3]) : "r"(a))
#define MMA_BF16(c, a, b0, b1) \
    asm volatile( \
        "mma.sync.aligned.m16n8k16.row.col.f32.bf16.bf16.f32 " \
        "{%0,%1,%2,%3}, {%4,%5,%6,%7}, {%8,%9}, {%0,%1,%2,%3};" \
        : "+f"((c)[0]), "+f"((c)[1]), "+f"((c)[2]), "+f"((c)[3]) \
        : "r"((a)[0]), "r"((a)[1]), "r"((a)[2]), "r"((a)[3]), "r"(b0), "r"(b1))

// smem layout (bytes). 144B row stride -> conflict-free ldmatrix/STS.
#define STRA 144
#define WSTR 144
#define W_W2HI 0
#define W_W2LO 9216
#define W_C1HI 18432
#define W_C1LO 27648
#define SM_A 36864
#define A_WARP 4608        // per-warp: 16x144 hi + 16x144 lo
#define SM_B2 73728
#define SM_CB1 (SM_B2 + 256)
#define SM_COUT (SM_B2 + 512)
#define SM_W1C (SM_B2 + 768)
#define SMEM_EDGE_BYTES (SM_B2 + 1024)

// ---------------- setup kernels ----------------
__global__ void k_init(const float* __restrict__ inputs,
                       const float* __restrict__ emb_w,
                       const float* __restrict__ emb_b) {
    int idx = blockIdx.x * blockDim.x + threadIdx.x;
    if (idx >= N_NODES * HD) return;
    int n = idx >> 6, j = idx & 63;
    float vx = inputs[n * 6 + 3], vy = inputs[n * 6 + 4], vz = inputs[n * 6 + 5];
    float sp = sqrtf(vx * vx + vy * vy + vz * vz);
    g_h[idx] = sp * emb_w[j] + emb_b[j];
    if (j < 3) {
        g_coord[0][n * 3 + j] = inputs[n * 6 + j];
        g_vel[n * 3 + j] = inputs[n * 6 + 3 + j];
    }
    if (idx < N_NODES) g_cnt[idx] = 0;
}

__global__ void k_hist(const int* __restrict__ recv) {
    int e = blockIdx.x * blockDim.x + threadIdx.x;
    if (e < N_EDGES) atomicAdd(&g_cnt[recv[e]], 1);
}

__global__ void k_scan() {
    __shared__ int part[1024];
    const int CH = (N_NODES + 1023) / 1024;
    int t = threadIdx.x;
    int s = 0;
    for (int i = 0; i < CH; i++) {
        int idx = t * CH + i;
        if (idx < N_NODES) s += g_cnt[idx];
    }
    part[t] = s;
    __syncthreads();
    for (int d = 1; d < 1024; d <<= 1) {
        int v = (t >= d) ? part[t - d] : 0;
        __syncthreads();
        part[t] += v;
        __syncthreads();
    }
    int run = (t == 0) ? 0 : part[t - 1];
    for (int i = 0; i < CH; i++) {
        int idx = t * CH + i;
        if (idx < N_NODES) {
            g_off[idx] = run;
            g_cur[idx] = run;
            int c = g_cnt[idx];
            g_inv[idx] = 1.0f / fmaxf((float)c, 1.0f);
            run += c;
            if (idx == N_NODES - 1) g_off[N_NODES] = run;
        }
    }
}

__global__ void k_fill(const int* __restrict__ recv) {
    int e = blockIdx.x * blockDim.x + threadIdx.x;
    if (e >= N_EDGES) return;
    int p = atomicAdd(&g_cur[recv[e]], 1);
    g_eid[p] = e;
}

// ---------------- per-layer node precompute: A, B, P, v_gate ----------------
__global__ void __launch_bounds__(256) k_node_pre(
    const float* __restrict__ w1a, const float* __restrict__ w1b,
    const float* __restrict__ b1,
    const float* __restrict__ nw1a, const float* __restrict__ nb1,
    const float* __restrict__ vw1, const float* __restrict__ vb1,
    const float* __restrict__ vw2, const float* __restrict__ vb2) {
    __shared__ float sH[8][68];
    int warp = threadIdx.x >> 5, lane = threadIdx.x & 31;
    int n = blockIdx.x * 8 + warp;
    if (n >= N_NODES) return;
    sH[warp][lane] = g_h[n * 64 + lane];
    sH[warp][lane + 32] = g_h[n * 64 + lane + 32];
    __syncwarp();
    float aA = b1[lane], aA2 = b1[lane + 32];
    float aB = 0.f, aB2 = 0.f;
    float aP = nb1[lane], aP2 = nb1[lane + 32];
    float aV = vb1[lane], aV2 = vb1[lane + 32];
#pragma unroll 4
    for (int k = 0; k < 64; k++) {
        float hv = sH[warp][k];
        aA += hv * w1a[k * 64 + lane];    aA2 += hv * w1a[k * 64 + lane + 32];
        aB += hv * w1b[k * 64 + lane];    aB2 += hv * w1b[k * 64 + lane + 32];
        aP += hv * nw1a[k * 64 + lane];   aP2 += hv * nw1a[k * 64 + lane + 32];
        aV += hv * vw1[k * 64 + lane];    aV2 += hv * vw1[k * 64 + lane + 32];
    }
    g_A[n * 64 + lane] = aA; g_A[n * 64 + lane + 32] = aA2;
    g_B[n * 64 + lane] = aB; g_B[n * 64 + lane + 32] = aB2;
    g_P[n * 64 + lane] = aP; g_P[n * 64 + lane + 32] = aP2;
    float q = siluf(aV), q2 = siluf(aV2);
    float part = q * vw2[lane] + q2 * vw2[lane + 32];
#pragma unroll
    for (int o = 16; o; o >>= 1) part += __shfl_xor_sync(0xffffffffu, part, o);
    if (lane == 0) g_vg[n] = part + vb2[0];
}

// ---------------- edge kernel: mma.sync bf16 (triple split) ----------------
// Software-pipelined front-end: next tile's indices prefetched under GEMM1,
// next tile's coords prefetched under epilogue1/GEMM2.
__global__ void __launch_bounds__(256, 3) k_edge(
    const int* __restrict__ send, const int* __restrict__ recv,
    const float* __restrict__ w2, const float* __restrict__ b2,
    const float* __restrict__ c1w, const float* __restrict__ cb1,
    const float* __restrict__ cout, const float* __restrict__ w1c,
    int parity, int writeEF) {
    extern __shared__ char sm8[];
    uint32_t sb = smem_u32(sm8);
    int tid = threadIdx.x, warp = tid >> 5, lane = tid & 31;

    // weights -> bf16 hi/lo in smem, row-major [k][n], 144B row stride
    for (int idx = tid; idx < 2048; idx += 256) {
        int k = idx >> 5, np = idx & 31;
        float a0 = w2[k * 64 + 2 * np], a1 = w2[k * 64 + 2 * np + 1];
        float c0 = c1w[k * 64 + 2 * np], c1v = c1w[k * 64 + 2 * np + 1];
        float a0h = bf_hi(a0), a1h = bf_hi(a1);
        float c0h = bf_hi(c0), c1h = bf_hi(c1v);
        uint32_t off = (uint32_t)(k * WSTR + np * 4);
        *(uint32_t*)(sm8 + W_W2HI + off) = pk_bf2(a0h, a1h);
        *(uint32_t*)(sm8 + W_W2LO + off) = pk_bf2(a0 - a0h, a1 - a1h);
        *(uint32_t*)(sm8 + W_C1HI + off) = pk_bf2(c0h, c1h);
        *(uint32_t*)(sm8 + W_C1LO + off) = pk_bf2(c0 - c0h, c1v - c1h);
    }
    float* sB2 = (float*)(sm8 + SM_B2);
    float* sCB1 = (float*)(sm8 + SM_CB1);
    float* sCOUT = (float*)(sm8 + SM_COUT);
    float* sW1C = (float*)(sm8 + SM_W1C);
    if (tid < 64) {
        sB2[tid] = b2[tid];
        sCB1[tid] = cb1[tid];
        sCOUT[tid] = cout[tid];
        sW1C[tid] = w1c[tid];
    }
    __syncthreads();

    const float* coord = g_coord[parity];
    char* aHiP = sm8 + SM_A + warp * A_WARP;
    char* aLoP = aHiP + 2304;
    uint32_t aHiB = sb + SM_A + warp * A_WARP;
    uint32_t aLoB = aHiB + 2304;

    // per-lane w1c pair (features 2*lane, 2*lane+1)
    float2 w1c2 = make_float2(sW1C[2 * lane], sW1C[2 * lane + 1]);

    // ldmatrix source addresses (per-thread)
    int m = lane >> 3, rr = lane & 7;
    uint32_t aRow = (uint32_t)(((m & 1) ? (8 + rr) : rr) * STRA + ((m >> 1) ? 16 : 0));
    uint32_t aAddrHi = aHiB + aRow;
    uint32_t aAddrLo = aLoB + aRow;
    // B: matrices 0,1 from HI (rows rr, 8+rr of the k-chunk); 2,3 from LO (+9216)
    uint32_t bOff = (uint32_t)((((m & 1) ? 8 : 0) + rr) * WSTR + ((m >> 1) ? 9216 : 0));
    uint32_t bG1 = sb + W_W2HI + bOff;
    uint32_t bG2 = sb + W_C1HI + bOff;

    const float2* b2v = (const float2*)sB2;
    const float2* cb1v = (const float2*)sCB1;
    const float2* coutv = (const float2*)sCOUT;

    int e16 = lane & 15;                 // this lane's edge (lanes 16-31 mirror)
    int r1 = lane >> 2, cq = lane & 3;   // C-frag mapping
    int r2 = r1 + 8;

    const int t0 = blockIdx.x * 8 + warp;
    const int tstride = gridDim.x * 8;

    // --- prologue: load first tile's indices + coords ---
    int sI = 0, rI = 0;
    float csx = 0.f, csy = 0.f, csz = 0.f, crx = 0.f, cry = 0.f, crz = 0.f;
    if (t0 < NTILE16) {
        int eM = t0 * 16 + e16;
        sI = send[eM];
        rI = recv[eM];
        csx = coord[sI * 3 + 0]; csy = coord[sI * 3 + 1]; csz = coord[sI * 3 + 2];
        crx = coord[rI * 3 + 0]; cry = coord[rI * 3 + 1]; crz = coord[rI * 3 + 2];
    }

    for (int t = t0; t < NTILE16; t += tstride) {
        int base = t * 16;
        float cdx = csx - crx;
        float cdy = csy - cry;
        float cdz = csz - crz;
        float rad = cdx * cdx + cdy * cdy + cdz * cdz;

        // ---- ef1 = silu(A[s]+B[r]+rad*w1c): cooperative, row-coalesced ----
#pragma unroll 4
        for (int e = 0; e < 16; e++) {
            int s = __shfl_sync(0xffffffffu, sI, e);
            int r = __shfl_sync(0xffffffffu, rI, e);
            float rd = __shfl_sync(0xffffffffu, rad, e);
            float2 a = *(const float2*)(g_A + s * 64 + 2 * lane);
            float2 b = *(const float2*)(g_B + r * 64 + 2 * lane);
            float z0 = siluf(a.x + b.x + rd * w1c2.x);
            float z1 = siluf(a.y + b.y + rd * w1c2.y);
            float h0 = bf_hi(z0), h1 = bf_hi(z1);
            *(uint32_t*)(aHiP + e * STRA + lane * 4) = pk_bf2(h0, h1);
            *(uint32_t*)(aLoP + e * STRA + lane * 4) = pk_bf2(z0 - h0, z1 - h1);
        }
        __syncwarp();

        // ---- prefetch next tile's indices (latency hidden under GEMM1) ----
        int tn = t + tstride;
        bool hasN = tn < NTILE16;
        int sN = 0, rN = 0;
        if (hasN) {
            int eN = tn * 16 + e16;
            sN = send[eN];
            rN = recv[eN];
        }

        // ---- GEMM1: ef = silu(ef1 @ W2 + b2) ----
        float acc[8][4];
#pragma unroll
        for (int jt = 0; jt < 8; jt++) {
            acc[jt][0] = 0.f; acc[jt][1] = 0.f; acc[jt][2] = 0.f; acc[jt][3] = 0.f;
        }
#pragma unroll
        for (int kc = 0; kc < 4; kc++) {
            uint32_t ah[4], al[4];
            LDSM4(ah, aAddrHi + kc * 32);
            LDSM4(al, aAddrLo + kc * 32);
#pragma unroll
            for (int jt = 0; jt < 8; jt++) {
                uint32_t bb[4];
                LDSM4T(bb, bG1 + kc * 2304 + jt * 16);
                MMA_BF16(acc[jt], ah, bb[0], bb[1]);
                MMA_BF16(acc[jt], al, bb[0], bb[1]);
                MMA_BF16(acc[jt], ah, bb[2], bb[3]);
            }
        }
        __syncwarp();

        // ---- prefetch next tile's coords (hidden under epi1 + GEMM2) ----
        if (hasN) {
            csx = coord[sN * 3 + 0]; csy = coord[sN * 3 + 1]; csz = coord[sN * 3 + 2];
            crx = coord[rN * 3 + 0]; cry = coord[rN * 3 + 1]; crz = coord[rN * 3 + 2];
        }

        // ---- epilogue1: silu + bias; re-split into smem (conflict-free) ----
#pragma unroll
        for (int jt = 0; jt < 8; jt++) {
            float2 bb = b2v[jt * 4 + cq];
            float e0 = siluf(acc[jt][0] + bb.x), e1 = siluf(acc[jt][1] + bb.y);
            float e2 = siluf(acc[jt][2] + bb.x), e3 = siluf(acc[jt][3] + bb.y);
            int jc = jt * 8 + cq * 2;
            float h0 = bf_hi(e0), h1 = bf_hi(e1), h2 = bf_hi(e2), h3 = bf_hi(e3);
            *(uint32_t*)(aHiP + r1 * STRA + jc * 2) = pk_bf2(h0, h1);
            *(uint32_t*)(aHiP + r2 * STRA + jc * 2) = pk_bf2(h2, h3);
            *(uint32_t*)(aLoP + r1 * STRA + jc * 2) = pk_bf2(e0 - h0, e1 - h1);
            *(uint32_t*)(aLoP + r2 * STRA + jc * 2) = pk_bf2(e2 - h2, e3 - h3);
        }
        __syncwarp();

        // ---- coalesced g_ef16 writeback from smem (ef = hi + lo) ----
        if (writeEF) {
#pragma unroll 4
            for (int e = 0; e < 16; e++) {
                uint32_t hp = *(const uint32_t*)(aHiP + e * STRA + lane * 4);
                uint32_t lp = *(const uint32_t*)(aLoP + e * STRA + lane * 4);
                __nv_bfloat162 hb = *reinterpret_cast<__nv_bfloat162*>(&hp);
                __nv_bfloat162 lb = *reinterpret_cast<__nv_bfloat162*>(&lp);
                float f0 = __bfloat162float(hb.x) + __bfloat162float(lb.x);
                float f1 = __bfloat162float(hb.y) + __bfloat162float(lb.y);
                *(__half2*)(g_ef16 + (size_t)(base + e) * 64 + 2 * lane) =
                    __floats2half2_rn(f0, f1);
            }
        }

        // ---- GEMM2: g = silu(ef @ C1 + cb1) ----
#pragma unroll
        for (int jt = 0; jt < 8; jt++) {
            acc[jt][0] = 0.f; acc[jt][1] = 0.f; acc[jt][2] = 0.f; acc[jt][3] = 0.f;
        }
#pragma unroll
        for (int kc = 0; kc < 4; kc++) {
            uint32_t ah[4], al[4];
            LDSM4(ah, aAddrHi + kc * 32);
            LDSM4(al, aAddrLo + kc * 32);
#pragma unroll
            for (int jt = 0; jt < 8; jt++) {
                uint32_t bb[4];
                LDSM4T(bb, bG2 + kc * 2304 + jt * 16);
                MMA_BF16(acc[jt], ah, bb[0], bb[1]);
                MMA_BF16(acc[jt], al, bb[0], bb[1]);
                MMA_BF16(acc[jt], ah, bb[2], bb[3]);
            }
        }

        // ---- epilogue2: cm = g . cout (quad reduce); trans = clip(cd*cm) ----
        float pr1 = 0.f, pr2 = 0.f;
#pragma unroll
        for (int jt = 0; jt < 8; jt++) {
            float2 cb = cb1v[jt * 4 + cq];
            float2 co = coutv[jt * 4 + cq];
            pr1 += siluf(acc[jt][0] + cb.x) * co.x + siluf(acc[jt][1] + cb.y) * co.y;
            pr2 += siluf(acc[jt][2] + cb.x) * co.x + siluf(acc[jt][3] + cb.y) * co.y;
        }
        pr1 += __shfl_xor_sync(0xffffffffu, pr1, 1);
        pr1 += __shfl_xor_sync(0xffffffffu, pr1, 2);
        pr2 += __shfl_xor_sync(0xffffffffu, pr2, 1);
        pr2 += __shfl_xor_sync(0xffffffffu, pr2, 2);
        float c1x = __shfl_sync(0xffffffffu, cdx, r1);
        float c1y = __shfl_sync(0xffffffffu, cdy, r1);
        float c1z = __shfl_sync(0xffffffffu, cdz, r1);
        float c2x = __shfl_sync(0xffffffffu, cdx, r2);
        float c2y = __shfl_sync(0xffffffffu, cdy, r2);
        float c2z = __shfl_sync(0xffffffffu, cdz, r2);
        if (cq == 0) {
            int e = base + r1;
            g_trans[e * 3 + 0] = fminf(fmaxf(c1x * pr1, -100.f), 100.f);
            g_trans[e * 3 + 1] = fminf(fmaxf(c1y * pr1, -100.f), 100.f);
            g_trans[e * 3 + 2] = fminf(fmaxf(c1z * pr1, -100.f), 100.f);
        } else if (cq == 1) {
            int e = base + r2;
            g_trans[e * 3 + 0] = fminf(fmaxf(c2x * pr2, -100.f), 100.f);
            g_trans[e * 3 + 1] = fminf(fmaxf(c2y * pr2, -100.f), 100.f);
            g_trans[e * 3 + 2] = fminf(fmaxf(c2z * pr2, -100.f), 100.f);
        }
        sI = sN;
        rI = rN;
        __syncwarp();
    }
}

// ---------------- per-layer node update ----------------
__global__ void __launch_bounds__(256) k_node(
    const float* __restrict__ nw1b, const float* __restrict__ nw2,
    const float* __restrict__ nb2, int parity, int doH) {
    __shared__ float sA[8][68];
    int warp = threadIdx.x >> 5, lane = threadIdx.x & 31;
    int n = blockIdx.x * 8 + warp;
    if (n >= N_NODES) return;
    int start = g_off[n];
    int deg = g_off[n + 1] - start;
    float aH = 0.f, aH2 = 0.f, ax = 0.f, ay = 0.f, az = 0.f;
    for (int base = 0; base < deg; base += 32) {
        int mm = deg - base;
        if (mm > 32) mm = 32;
        int e = 0;
        if (lane < mm) {
            e = g_eid[start + base + lane];
            ax += g_trans[e * 3 + 0];
            ay += g_trans[e * 3 + 1];
            az += g_trans[e * 3 + 2];
        }
        if (doH) {
            const uint32_t* efb = (const uint32_t*)g_ef16;
            int tt = 0;
            // 4-deep unrolled gather: 4 independent 128B-row loads in flight
            for (; tt + 4 <= mm; tt += 4) {
                int e0 = __shfl_sync(0xffffffffu, e, tt);
                int e1 = __shfl_sync(0xffffffffu, e, tt + 1);
                int e2 = __shfl_sync(0xffffffffu, e, tt + 2);
                int e3 = __shfl_sync(0xffffffffu, e, tt + 3);
                uint32_t v0 = efb[(size_t)e0 * 32 + lane];
                uint32_t v1 = efb[(size_t)e1 * 32 + lane];
                uint32_t v2 = efb[(size_t)e2 * 32 + lane];
                uint32_t v3 = efb[(size_t)e3 * 32 + lane];
                float2 f0 = __half22float2(*reinterpret_cast<__half2*>(&v0));
                float2 f1 = __half22float2(*reinterpret_cast<__half2*>(&v1));
                float2 f2 = __half22float2(*reinterpret_cast<__half2*>(&v2));
                float2 f3 = __half22float2(*reinterpret_cast<__half2*>(&v3));
                aH += (f0.x + f1.x) + (f2.x + f3.x);
                aH2 += (f0.y + f1.y) + (f2.y + f3.y);
            }
            for (; tt < mm; tt++) {
                int ee = __shfl_sync(0xffffffffu, e, tt);
                uint32_t v = efb[(size_t)ee * 32 + lane];
                float2 f = __half22float2(*reinterpret_cast<__half2*>(&v));
                aH += f.x;
                aH2 += f.y;
            }
        }
    }
#pragma unroll
    for (int o = 16; o; o >>= 1) {
        ax += __shfl_xor_sync(0xffffffffu, ax, o);
        ay += __shfl_xor_sync(0xffffffffu, ay, o);
        az += __shfl_xor_sync(0xffffffffu, az, o);
    }
    if (doH) {
        // lane holds agg for features 2*lane, 2*lane+1
        sA[warp][2 * lane] = aH;
        sA[warp][2 * lane + 1] = aH2;
        __syncwarp();
        float aQ = g_P[n * 64 + lane], aQ2 = g_P[n * 64 + lane + 32];
#pragma unroll 4
        for (int k = 0; k < 64; k++) {
            float v = sA[warp][k];
            aQ += v * nw1b[k * 64 + lane];
            aQ2 += v * nw1b[k * 64 + lane + 32];
        }
        float t1 = siluf(aQ), t2 = siluf(aQ2);
        __syncwarp();
        sA[warp][lane] = t1;
        sA[warp][lane + 32] = t2;
        __syncwarp();
        float aO = nb2[lane] + g_h[n * 64 + lane];
        float aO2 = nb2[lane + 32] + g_h[n * 64 + lane + 32];
#pragma unroll 4
        for (int k = 0; k < 64; k++) {
            float v = sA[warp][k];
            aO += v * nw2[k * 64 + lane];
            aO2 += v * nw2[k * 64 + lane + 32];
        }
        g_h[n * 64 + lane] = aO;
        g_h[n * 64 + lane + 32] = aO2;
    }
    if (lane < 3) {
        float iv = g_inv[n];
        float agg = (lane == 0) ? ax : ((lane == 1) ? ay : az);
        float vo = g_vel[n * 3 + lane];
        float vn = agg * iv + g_vg[n] * vo;
        g_vel[n * 3 + lane] = vn;
        g_coord[parity ^ 1][n * 3 + lane] = g_coord[parity][n * 3 + lane] + vn;
    }
}

__global__ void k_out(float* __restrict__ out) {
    int idx = blockIdx.x * blockDim.x + threadIdx.x;
    if (idx >= N_NODES * 3) return;
    int n = idx / 3, c = idx % 3;
    out[n * 6 + c] = g_coord[0][idx];
    out[n * 6 + 3 + c] = g_vel[idx];
}

// ---------------- host launcher ----------------
extern "C" void kernel_launch(void* const* d_in, const int* in_sizes, int n_in,
                              void* d_out, int out_size) {
    const float* inputs = (const float*)d_in[0];
    const int* send = (const int*)d_in[2];
    const int* recv = (const int*)d_in[3];
    const float* emb_w = (const float*)d_in[4];
    const float* emb_b = (const float*)d_in[5];
    const float* ew1 = (const float*)d_in[6];   // (L,129,64)
    const float* eb1 = (const float*)d_in[7];
    const float* ew2 = (const float*)d_in[8];   // (L,64,64)
    const float* eb2 = (const float*)d_in[9];
    const float* nw1 = (const float*)d_in[10];  // (L,128,64)
    const float* nb1 = (const float*)d_in[11];
    const float* nw2 = (const float*)d_in[12];
    const float* nb2 = (const float*)d_in[13];
    const float* cw1 = (const float*)d_in[14];
    const float* cb1 = (const float*)d_in[15];
    const float* cwo = (const float*)d_in[16];
    const float* vw1 = (const float*)d_in[17];
    const float* vb1 = (const float*)d_in[18];
    const float* vw2 = (const float*)d_in[19];
    const float* vb2 = (const float*)d_in[20];
    float* out = (float*)d_out;

    cudaFuncSetAttribute(k_edge, cudaFuncAttributeMaxDynamicSharedMemorySize,
                         SMEM_EDGE_BYTES);

    k_init<<<(N_NODES * HD + 255) / 256, 256>>>(inputs, emb_w, emb_b);
    k_hist<<<(N_EDGES + 511) / 512, 512>>>(recv);
    k_scan<<<1, 1024>>>();
    k_fill<<<(N_EDGES + 511) / 512, 512>>>(recv);

    for (int l = 0; l < NLAYERS; l++) {
        int par = l & 1;
        int last = (l == NLAYERS - 1);
        k_node_pre<<<(N_NODES + 7) / 8, 256>>>(
            ew1 + l * 8256, ew1 + l * 8256 + 4096, eb1 + l * 64,
            nw1 + l * 8192, nb1 + l * 64,
            vw1 + l * 4096, vb1 + l * 64, vw2 + l * 64, vb2 + l);
        k_edge<<<444, 256, SMEM_EDGE_BYTES>>>(
            send, recv, ew2 + l * 4096, eb2 + l * 64,
            cw1 + l * 4096, cb1 + l * 64, cwo + l * 64,
            ew1 + l * 8256 + 8192, par, last ? 0 : 1);
        k_node<<<(N_NODES + 7) / 8, 256>>>(
            nw1 + l * 8192 + 4096, nw2 + l * 4096, nb2 + l * 64, par,
            last ? 0 : 1);
    }
    k_out<<<(N_NODES * 3 + 255) / 256, 256>>>(out);
}

// round 15
// speedup vs baseline: 1.4657x; 1.4657x over previous
#include <cuda_runtime.h>
#include <cuda_bf16.h>
#include <cuda_fp16.h>
#include <cstdint>

#define N_NODES 20000
#define N_EDGES 1280000
#define HD 64
#define NLAYERS 4
#define NTILE16 (N_EDGES / 16)   // 80000 warp-tiles of 16 edges

// ---------------- device scratch (no cudaMalloc allowed) ----------------
__device__ float g_h[N_NODES * HD];
__device__ float g_A[N_NODES * HD];
__device__ float g_B[N_NODES * HD];
__device__ float g_P[N_NODES * HD];
__device__ float g_vg[N_NODES];
__device__ float g_coord[2][N_NODES * 3];
__device__ float g_vel[N_NODES * 3];
__device__ __half g_ef16[(size_t)N_EDGES * HD];   // per-edge features, fp16
__device__ float g_trans[N_EDGES * 3];
__device__ int   g_cnt[N_NODES];
__device__ int   g_off[N_NODES + 1];
__device__ int   g_cur[N_NODES];
__device__ int   g_eid[N_EDGES];
__device__ float g_inv[N_NODES];

__device__ __forceinline__ float siluf(float x) {
    return __fdividef(x, 1.0f + __expf(-x));
}
__device__ __forceinline__ uint32_t smem_u32(const void* p) {
    uint32_t a;
    asm("{ .reg .u64 t; cvta.to.shared.u64 t, %1; cvt.u32.u64 %0, t; }"
        : "=r"(a) : "l"(p));
    return a;
}
__device__ __forceinline__ uint32_t pk_bf2(float a, float b) {
    __nv_bfloat162 t = __floats2bfloat162_rn(a, b);
    return reinterpret_cast<uint32_t&>(t);
}
__device__ __forceinline__ float bf_hi(float v) {
    return __bfloat162float(__float2bfloat16(v));
}

#define LDSM4(r, a) \
    asm volatile("ldmatrix.sync.aligned.m8n8.x4.shared.b16 {%0,%1,%2,%3}, [%4];" \
        : "=r"((r)[0]), "=r"((r)[1]), "=r"((r)[2]), "=r"((r)[3]) : "r"(a))
#define LDSM4T(r, a) \
    asm volatile("ldmatrix.sync.aligned.m8n8.x4.trans.shared.b16 {%0,%1,%2,%3}, [%4];" \
        : "=r"((r)[0]), "=r"((r)[1]), "=r"((r)[2]), "=r"((r)[3]) : "r"(a))
#define MMA_BF16(c, a, b0, b1) \
    asm volatile( \
        "mma.sync.aligned.m16n8k16.row.col.f32.bf16.bf16.f32 " \
        "{%0,%1,%2,%3}, {%4,%5,%6,%7}, {%8,%9}, {%0,%1,%2,%3};" \
        : "+f"((c)[0]), "+f"((c)[1]), "+f"((c)[2]), "+f"((c)[3]) \
        : "r"((a)[0]), "r"((a)[1]), "r"((a)[2]), "r"((a)[3]), "r"(b0), "r"(b1))

// smem layout (bytes). 144B row stride -> conflict-free ldmatrix/STS.
#define STRA 144
#define WSTR 144
#define W_W2HI 0
#define W_W2LO 9216
#define W_C1HI 18432
#define W_C1LO 27648
#define SM_A 36864
#define A_WARP 4608        // per-warp: 16x144 hi + 16x144 lo
#define SM_B2 73728
#define SM_CB1 (SM_B2 + 256)
#define SM_COUT (SM_B2 + 512)
#define SM_W1C (SM_B2 + 768)
#define SMEM_EDGE_BYTES (SM_B2 + 1024)

// ---------------- setup kernels ----------------
__global__ void k_init(const float* __restrict__ inputs,
                       const float* __restrict__ emb_w,
                       const float* __restrict__ emb_b) {
    int idx = blockIdx.x * blockDim.x + threadIdx.x;
    if (idx >= N_NODES * HD) return;
    int n = idx >> 6, j = idx & 63;
    float vx = inputs[n * 6 + 3], vy = inputs[n * 6 + 4], vz = inputs[n * 6 + 5];
    float sp = sqrtf(vx * vx + vy * vy + vz * vz);
    g_h[idx] = sp * emb_w[j] + emb_b[j];
    if (j < 3) {
        g_coord[0][n * 3 + j] = inputs[n * 6 + j];
        g_vel[n * 3 + j] = inputs[n * 6 + 3 + j];
    }
    if (idx < N_NODES) g_cnt[idx] = 0;
}

__global__ void k_hist(const int* __restrict__ recv) {
    int e = blockIdx.x * blockDim.x + threadIdx.x;
    if (e < N_EDGES) atomicAdd(&g_cnt[recv[e]], 1);
}

__global__ void k_scan() {
    __shared__ int part[1024];
    const int CH = (N_NODES + 1023) / 1024;
    int t = threadIdx.x;
    int s = 0;
    for (int i = 0; i < CH; i++) {
        int idx = t * CH + i;
        if (idx < N_NODES) s += g_cnt[idx];
    }
    part[t] = s;
    __syncthreads();
    for (int d = 1; d < 1024; d <<= 1) {
        int v = (t >= d) ? part[t - d] : 0;
        __syncthreads();
        part[t] += v;
        __syncthreads();
    }
    int run = (t == 0) ? 0 : part[t - 1];
    for (int i = 0; i < CH; i++) {
        int idx = t * CH + i;
        if (idx < N_NODES) {
            g_off[idx] = run;
            g_cur[idx] = run;
            int c = g_cnt[idx];
            g_inv[idx] = 1.0f / fmaxf((float)c, 1.0f);
            run += c;
            if (idx == N_NODES - 1) g_off[N_NODES] = run;
        }
    }
}

__global__ void k_fill(const int* __restrict__ recv) {
    int e = blockIdx.x * blockDim.x + threadIdx.x;
    if (e >= N_EDGES) return;
    int p = atomicAdd(&g_cur[recv[e]], 1);
    g_eid[p] = e;
}

// ---------------- per-layer node precompute: A, B, P, v_gate ----------------
__global__ void __launch_bounds__(256) k_node_pre(
    const float* __restrict__ w1a, const float* __restrict__ w1b,
    const float* __restrict__ b1,
    const float* __restrict__ nw1a, const float* __restrict__ nb1,
    const float* __restrict__ vw1, const float* __restrict__ vb1,
    const float* __restrict__ vw2, const float* __restrict__ vb2) {
    __shared__ float sH[8][68];
    int warp = threadIdx.x >> 5, lane = threadIdx.x & 31;
    int n = blockIdx.x * 8 + warp;
    if (n >= N_NODES) return;
    sH[warp][lane] = g_h[n * 64 + lane];
    sH[warp][lane + 32] = g_h[n * 64 + lane + 32];
    __syncwarp();
    float aA = b1[lane], aA2 = b1[lane + 32];
    float aB = 0.f, aB2 = 0.f;
    float aP = nb1[lane], aP2 = nb1[lane + 32];
    float aV = vb1[lane], aV2 = vb1[lane + 32];
#pragma unroll 4
    for (int k = 0; k < 64; k++) {
        float hv = sH[warp][k];
        aA += hv * w1a[k * 64 + lane];    aA2 += hv * w1a[k * 64 + lane + 32];
        aB += hv * w1b[k * 64 + lane];    aB2 += hv * w1b[k * 64 + lane + 32];
        aP += hv * nw1a[k * 64 + lane];   aP2 += hv * nw1a[k * 64 + lane + 32];
        aV += hv * vw1[k * 64 + lane];    aV2 += hv * vw1[k * 64 + lane + 32];
    }
    g_A[n * 64 + lane] = aA; g_A[n * 64 + lane + 32] = aA2;
    g_B[n * 64 + lane] = aB; g_B[n * 64 + lane + 32] = aB2;
    g_P[n * 64 + lane] = aP; g_P[n * 64 + lane + 32] = aP2;
    float q = siluf(aV), q2 = siluf(aV2);
    float part = q * vw2[lane] + q2 * vw2[lane + 32];
#pragma unroll
    for (int o = 16; o; o >>= 1) part += __shfl_xor_sync(0xffffffffu, part, o);
    if (lane == 0) g_vg[n] = part + vb2[0];
}

// ---------------- edge kernel: mma.sync bf16 (triple split) ----------------
__global__ void __launch_bounds__(256, 3) k_edge(
    const int* __restrict__ send, const int* __restrict__ recv,
    const float* __restrict__ w2, const float* __restrict__ b2,
    const float* __restrict__ c1w, const float* __restrict__ cb1,
    const float* __restrict__ cout, const float* __restrict__ w1c,
    int parity, int writeEF) {
    extern __shared__ char sm8[];
    uint32_t sb = smem_u32(sm8);
    int tid = threadIdx.x, warp = tid >> 5, lane = tid & 31;

    // weights -> bf16 hi/lo in smem, row-major [k][n], 144B row stride
    for (int idx = tid; idx < 2048; idx += 256) {
        int k = idx >> 5, np = idx & 31;
        float a0 = w2[k * 64 + 2 * np], a1 = w2[k * 64 + 2 * np + 1];
        float c0 = c1w[k * 64 + 2 * np], c1v = c1w[k * 64 + 2 * np + 1];
        float a0h = bf_hi(a0), a1h = bf_hi(a1);
        float c0h = bf_hi(c0), c1h = bf_hi(c1v);
        uint32_t off = (uint32_t)(k * WSTR + np * 4);
        *(uint32_t*)(sm8 + W_W2HI + off) = pk_bf2(a0h, a1h);
        *(uint32_t*)(sm8 + W_W2LO + off) = pk_bf2(a0 - a0h, a1 - a1h);
        *(uint32_t*)(sm8 + W_C1HI + off) = pk_bf2(c0h, c1h);
        *(uint32_t*)(sm8 + W_C1LO + off) = pk_bf2(c0 - c0h, c1v - c1h);
    }
    float* sB2 = (float*)(sm8 + SM_B2);
    float* sCB1 = (float*)(sm8 + SM_CB1);
    float* sCOUT = (float*)(sm8 + SM_COUT);
    float* sW1C = (float*)(sm8 + SM_W1C);
    if (tid < 64) {
        sB2[tid] = b2[tid];
        sCB1[tid] = cb1[tid];
        sCOUT[tid] = cout[tid];
        sW1C[tid] = w1c[tid];
    }
    __syncthreads();

    const float* coord = g_coord[parity];
    char* aHiP = sm8 + SM_A + warp * A_WARP;
    char* aLoP = aHiP + 2304;
    uint32_t aHiB = sb + SM_A + warp * A_WARP;
    uint32_t aLoB = aHiB + 2304;

    // per-lane w1c pair (features 2*lane, 2*lane+1)
    float2 w1c2 = make_float2(sW1C[2 * lane], sW1C[2 * lane + 1]);

    // ldmatrix source addresses (per-thread)
    int m = lane >> 3, rr = lane & 7;
    uint32_t aRow = (uint32_t)(((m & 1) ? (8 + rr) : rr) * STRA + ((m >> 1) ? 16 : 0));
    uint32_t aAddrHi = aHiB + aRow;
    uint32_t aAddrLo = aLoB + aRow;
    // B: matrices 0,1 from HI (rows rr, 8+rr of the k-chunk); 2,3 from LO (+9216)
    uint32_t bOff = (uint32_t)((((m & 1) ? 8 : 0) + rr) * WSTR + ((m >> 1) ? 9216 : 0));
    uint32_t bG1 = sb + W_W2HI + bOff;
    uint32_t bG2 = sb + W_C1HI + bOff;

    const float2* b2v = (const float2*)sB2;
    const float2* cb1v = (const float2*)sCB1;
    const float2* coutv = (const float2*)sCOUT;

    int e16 = lane & 15;                 // this lane's edge (lanes 16-31 mirror)
    int r1 = lane >> 2, cq = lane & 3;   // C-frag mapping
    int r2 = r1 + 8;

    for (int t = blockIdx.x * 8 + warp; t < NTILE16; t += gridDim.x * 8) {
        int base = t * 16;
        int eMe = base + e16;
        int sI = send[eMe], rI = recv[eMe];
        float cdx = coord[sI * 3 + 0] - coord[rI * 3 + 0];
        float cdy = coord[sI * 3 + 1] - coord[rI * 3 + 1];
        float cdz = coord[sI * 3 + 2] - coord[rI * 3 + 2];
        float rad = cdx * cdx + cdy * cdy + cdz * cdz;

        // ---- ef1 = silu(A[s]+B[r]+rad*w1c): cooperative, row-coalesced ----
#pragma unroll 4
        for (int e = 0; e < 16; e++) {
            int s = __shfl_sync(0xffffffffu, sI, e);
            int r = __shfl_sync(0xffffffffu, rI, e);
            float rd = __shfl_sync(0xffffffffu, rad, e);
            float2 a = *(const float2*)(g_A + s * 64 + 2 * lane);
            float2 b = *(const float2*)(g_B + r * 64 + 2 * lane);
            float z0 = siluf(a.x + b.x + rd * w1c2.x);
            float z1 = siluf(a.y + b.y + rd * w1c2.y);
            float h0 = bf_hi(z0), h1 = bf_hi(z1);
            *(uint32_t*)(aHiP + e * STRA + lane * 4) = pk_bf2(h0, h1);
            *(uint32_t*)(aLoP + e * STRA + lane * 4) = pk_bf2(z0 - h0, z1 - h1);
        }
        __syncwarp();

        // ---- GEMM1: ef = silu(ef1 @ W2 + b2) ----
        float acc[8][4];
#pragma unroll
        for (int jt = 0; jt < 8; jt++) {
            acc[jt][0] = 0.f; acc[jt][1] = 0.f; acc[jt][2] = 0.f; acc[jt][3] = 0.f;
        }
#pragma unroll
        for (int kc = 0; kc < 4; kc++) {
            uint32_t ah[4], al[4];
            LDSM4(ah, aAddrHi + kc * 32);
            LDSM4(al, aAddrLo + kc * 32);
#pragma unroll
            for (int jt = 0; jt < 8; jt++) {
                uint32_t bb[4];
                LDSM4T(bb, bG1 + kc * 2304 + jt * 16);
                MMA_BF16(acc[jt], ah, bb[0], bb[1]);
                MMA_BF16(acc[jt], al, bb[0], bb[1]);
                MMA_BF16(acc[jt], ah, bb[2], bb[3]);
            }
        }
        __syncwarp();

        // ---- epilogue1: silu + bias; re-split into smem (conflict-free) ----
#pragma unroll
        for (int jt = 0; jt < 8; jt++) {
            float2 bb = b2v[jt * 4 + cq];
            float e0 = siluf(acc[jt][0] + bb.x), e1 = siluf(acc[jt][1] + bb.y);
            float e2 = siluf(acc[jt][2] + bb.x), e3 = siluf(acc[jt][3] + bb.y);
            int jc = jt * 8 + cq * 2;
            float h0 = bf_hi(e0), h1 = bf_hi(e1), h2 = bf_hi(e2), h3 = bf_hi(e3);
            *(uint32_t*)(aHiP + r1 * STRA + jc * 2) = pk_bf2(h0, h1);
            *(uint32_t*)(aHiP + r2 * STRA + jc * 2) = pk_bf2(h2, h3);
            *(uint32_t*)(aLoP + r1 * STRA + jc * 2) = pk_bf2(e0 - h0, e1 - h1);
            *(uint32_t*)(aLoP + r2 * STRA + jc * 2) = pk_bf2(e2 - h2, e3 - h3);
        }
        __syncwarp();

        // ---- coalesced g_ef16 writeback from smem (ef = hi + lo) ----
        if (writeEF) {
#pragma unroll 4
            for (int e = 0; e < 16; e++) {
                uint32_t hp = *(const uint32_t*)(aHiP + e * STRA + lane * 4);
                uint32_t lp = *(const uint32_t*)(aLoP + e * STRA + lane * 4);
                __nv_bfloat162 hb = *reinterpret_cast<__nv_bfloat162*>(&hp);
                __nv_bfloat162 lb = *reinterpret_cast<__nv_bfloat162*>(&lp);
                float f0 = __bfloat162float(hb.x) + __bfloat162float(lb.x);
                float f1 = __bfloat162float(hb.y) + __bfloat162float(lb.y);
                *(__half2*)(g_ef16 + (size_t)(base + e) * 64 + 2 * lane) =
                    __floats2half2_rn(f0, f1);
            }
        }

        // ---- GEMM2: g = silu(ef @ C1 + cb1) ----
#pragma unroll
        for (int jt = 0; jt < 8; jt++) {
            acc[jt][0] = 0.f; acc[jt][1] = 0.f; acc[jt][2] = 0.f; acc[jt][3] = 0.f;
        }
#pragma unroll
        for (int kc = 0; kc < 4; kc++) {
            uint32_t ah[4], al[4];
            LDSM4(ah, aAddrHi + kc * 32);
            LDSM4(al, aAddrLo + kc * 32);
#pragma unroll
            for (int jt = 0; jt < 8; jt++) {
                uint32_t bb[4];
                LDSM4T(bb, bG2 + kc * 2304 + jt * 16);
                MMA_BF16(acc[jt], ah, bb[0], bb[1]);
                MMA_BF16(acc[jt], al, bb[0], bb[1]);
                MMA_BF16(acc[jt], ah, bb[2], bb[3]);
            }
        }

        // ---- epilogue2: cm = g . cout (quad reduce); trans = clip(cd*cm) ----
        float pr1 = 0.f, pr2 = 0.f;
#pragma unroll
        for (int jt = 0; jt < 8; jt++) {
            float2 cb = cb1v[jt * 4 + cq];
            float2 co = coutv[jt * 4 + cq];
            pr1 += siluf(acc[jt][0] + cb.x) * co.x + siluf(acc[jt][1] + cb.y) * co.y;
            pr2 += siluf(acc[jt][2] + cb.x) * co.x + siluf(acc[jt][3] + cb.y) * co.y;
        }
        pr1 += __shfl_xor_sync(0xffffffffu, pr1, 1);
        pr1 += __shfl_xor_sync(0xffffffffu, pr1, 2);
        pr2 += __shfl_xor_sync(0xffffffffu, pr2, 1);
        pr2 += __shfl_xor_sync(0xffffffffu, pr2, 2);
        float c1x = __shfl_sync(0xffffffffu, cdx, r1);
        float c1y = __shfl_sync(0xffffffffu, cdy, r1);
        float c1z = __shfl_sync(0xffffffffu, cdz, r1);
        float c2x = __shfl_sync(0xffffffffu, cdx, r2);
        float c2y = __shfl_sync(0xffffffffu, cdy, r2);
        float c2z = __shfl_sync(0xffffffffu, cdz, r2);
        if (cq == 0) {
            int e = base + r1;
            g_trans[e * 3 + 0] = fminf(fmaxf(c1x * pr1, -100.f), 100.f);
            g_trans[e * 3 + 1] = fminf(fmaxf(c1y * pr1, -100.f), 100.f);
            g_trans[e * 3 + 2] = fminf(fmaxf(c1z * pr1, -100.f), 100.f);
        } else if (cq == 1) {
            int e = base + r2;
            g_trans[e * 3 + 0] = fminf(fmaxf(c2x * pr2, -100.f), 100.f);
            g_trans[e * 3 + 1] = fminf(fmaxf(c2y * pr2, -100.f), 100.f);
            g_trans[e * 3 + 2] = fminf(fmaxf(c2z * pr2, -100.f), 100.f);
        }
        __syncwarp();
    }
}

// ---------------- per-layer node update ----------------
__global__ void __launch_bounds__(256) k_node(
    const float* __restrict__ nw1b, const float* __restrict__ nw2,
    const float* __restrict__ nb2, int parity, int doH) {
    __shared__ float sA[8][68];
    int warp = threadIdx.x >> 5, lane = threadIdx.x & 31;
    int n = blockIdx.x * 8 + warp;
    if (n >= N_NODES) return;
    int start = g_off[n];
    int deg = g_off[n + 1] - start;
    float aH = 0.f, aH2 = 0.f, ax = 0.f, ay = 0.f, az = 0.f;
    for (int base = 0; base < deg; base += 32) {
        int mm = deg - base;
        if (mm > 32) mm = 32;
        int e = 0;
        if (lane < mm) {
            e = g_eid[start + base + lane];
            ax += g_trans[e * 3 + 0];
            ay += g_trans[e * 3 + 1];
            az += g_trans[e * 3 + 2];
        }
        if (doH) {
            const uint32_t* efb = (const uint32_t*)g_ef16;
            int tt = 0;
            // 4-deep unrolled gather: 4 independent 128B-row loads in flight
            for (; tt + 4 <= mm; tt += 4) {
                int e0 = __shfl_sync(0xffffffffu, e, tt);
                int e1 = __shfl_sync(0xffffffffu, e, tt + 1);
                int e2 = __shfl_sync(0xffffffffu, e, tt + 2);
                int e3 = __shfl_sync(0xffffffffu, e, tt + 3);
                uint32_t v0 = efb[(size_t)e0 * 32 + lane];
                uint32_t v1 = efb[(size_t)e1 * 32 + lane];
                uint32_t v2 = efb[(size_t)e2 * 32 + lane];
                uint32_t v3 = efb[(size_t)e3 * 32 + lane];
                float2 f0 = __half22float2(*reinterpret_cast<__half2*>(&v0));
                float2 f1 = __half22float2(*reinterpret_cast<__half2*>(&v1));
                float2 f2 = __half22float2(*reinterpret_cast<__half2*>(&v2));
                float2 f3 = __half22float2(*reinterpret_cast<__half2*>(&v3));
                aH += (f0.x + f1.x) + (f2.x + f3.x);
                aH2 += (f0.y + f1.y) + (f2.y + f3.y);
            }
            for (; tt < mm; tt++) {
                int ee = __shfl_sync(0xffffffffu, e, tt);
                uint32_t v = efb[(size_t)ee * 32 + lane];
                float2 f = __half22float2(*reinterpret_cast<__half2*>(&v));
                aH += f.x;
                aH2 += f.y;
            }
        }
    }
#pragma unroll
    for (int o = 16; o; o >>= 1) {
        ax += __shfl_xor_sync(0xffffffffu, ax, o);
        ay += __shfl_xor_sync(0xffffffffu, ay, o);
        az += __shfl_xor_sync(0xffffffffu, az, o);
    }
    if (doH) {
        // lane holds agg for features 2*lane, 2*lane+1
        sA[warp][2 * lane] = aH;
        sA[warp][2 * lane + 1] = aH2;
        __syncwarp();
        float aQ = g_P[n * 64 + lane], aQ2 = g_P[n * 64 + lane + 32];
#pragma unroll 4
        for (int k = 0; k < 64; k++) {
            float v = sA[warp][k];
            aQ += v * nw1b[k * 64 + lane];
            aQ2 += v * nw1b[k * 64 + lane + 32];
        }
        float t1 = siluf(aQ), t2 = siluf(aQ2);
        __syncwarp();
        sA[warp][lane] = t1;
        sA[warp][lane + 32] = t2;
        __syncwarp();
        float aO = nb2[lane] + g_h[n * 64 + lane];
        float aO2 = nb2[lane + 32] + g_h[n * 64 + lane + 32];
#pragma unroll 4
        for (int k = 0; k < 64; k++) {
            float v = sA[warp][k];
            aO += v * nw2[k * 64 + lane];
            aO2 += v * nw2[k * 64 + lane + 32];
        }
        g_h[n * 64 + lane] = aO;
        g_h[n * 64 + lane + 32] = aO2;
    }
    if (lane < 3) {
        float iv = g_inv[n];
        float agg = (lane == 0) ? ax : ((lane == 1) ? ay : az);
        float vo = g_vel[n * 3 + lane];
        float vn = agg * iv + g_vg[n] * vo;
        g_vel[n * 3 + lane] = vn;
        g_coord[parity ^ 1][n * 3 + lane] = g_coord[parity][n * 3 + lane] + vn;
    }
}

__global__ void k_out(float* __restrict__ out) {
    int idx = blockIdx.x * blockDim.x + threadIdx.x;
    if (idx >= N_NODES * 3) return;
    int n = idx / 3, c = idx % 3;
    out[n * 6 + c] = g_coord[0][idx];
    out[n * 6 + 3 + c] = g_vel[idx];
}

// ---------------- host launcher ----------------
extern "C" void kernel_launch(void* const* d_in, const int* in_sizes, int n_in,
                              void* d_out, int out_size) {
    const float* inputs = (const float*)d_in[0];
    const int* send = (const int*)d_in[2];
    const int* recv = (const int*)d_in[3];
    const float* emb_w = (const float*)d_in[4];
    const float* emb_b = (const float*)d_in[5];
    const float* ew1 = (const float*)d_in[6];   // (L,129,64)
    const float* eb1 = (const float*)d_in[7];
    const float* ew2 = (const float*)d_in[8];   // (L,64,64)
    const float* eb2 = (const float*)d_in[9];
    const float* nw1 = (const float*)d_in[10];  // (L,128,64)
    const float* nb1 = (const float*)d_in[11];
    const float* nw2 = (const float*)d_in[12];
    const float* nb2 = (const float*)d_in[13];
    const float* cw1 = (const float*)d_in[14];
    const float* cb1 = (const float*)d_in[15];
    const float* cwo = (const float*)d_in[16];
    const float* vw1 = (const float*)d_in[17];
    const float* vb1 = (const float*)d_in[18];
    const float* vw2 = (const float*)d_in[19];
    const float* vb2 = (const float*)d_in[20];
    float* out = (float*)d_out;

    cudaFuncSetAttribute(k_edge, cudaFuncAttributeMaxDynamicSharedMemorySize,
                         SMEM_EDGE_BYTES);

    k_init<<<(N_NODES * HD + 255) / 256, 256>>>(inputs, emb_w, emb_b);
    k_hist<<<(N_EDGES + 511) / 512, 512>>>(recv);
    k_scan<<<1, 1024>>>();
    k_fill<<<(N_EDGES + 511) / 512, 512>>>(recv);

    for (int l = 0; l < NLAYERS; l++) {
        int par = l & 1;
        int last = (l == NLAYERS - 1);
        k_node_pre<<<(N_NODES + 7) / 8, 256>>>(
            ew1 + l * 8256, ew1 + l * 8256 + 4096, eb1 + l * 64,
            nw1 + l * 8192, nb1 + l * 64,
            vw1 + l * 4096, vb1 + l * 64, vw2 + l * 64, vb2 + l);
        k_edge<<<444, 256, SMEM_EDGE_BYTES>>>(
            send, recv, ew2 + l * 4096, eb2 + l * 64,
            cw1 + l * 4096, cb1 + l * 64, cwo + l * 64,
            ew1 + l * 8256 + 8192, par, last ? 0 : 1);
        k_node<<<(N_NODES + 7) / 8, 256>>>(
            nw1 + l * 8192 + 4096, nw2 + l * 4096, nb2 + l * 64, par,
            last ? 0 : 1);
    }
    k_out<<<(N_NODES * 3 + 255) / 256, 256>>>(out);
}

// round 17
// speedup vs baseline: 1.5001x; 1.0235x over previous
#include <cuda_runtime.h>
#include <cuda_bf16.h>
#include <cuda_fp16.h>
#include <cstdint>

#define N_NODES 20000
#define N_EDGES 1280000
#define HD 64
#define NLAYERS 4
#define NTILE16 (N_EDGES / 16)   // 80000 warp-tiles of 16 edges

// ---------------- device scratch (no cudaMalloc allowed) ----------------
__device__ float g_h[N_NODES * HD];
__device__ float g_A[N_NODES * HD];
__device__ float g_B[N_NODES * HD];
__device__ float g_P[N_NODES * HD];
__device__ float g_vg[N_NODES];
__device__ float g_coord[2][N_NODES * 3];
__device__ float g_vel[N_NODES * 3];
__device__ __half g_ef16[(size_t)N_EDGES * HD];   // per-edge features, CSR order
__device__ float g_trans[N_EDGES * 3];            // CSR order
__device__ int   g_cnt[N_NODES];
__device__ int   g_off[N_NODES + 1];
__device__ int   g_cur[N_NODES];
__device__ int   g_pos[N_EDGES];    // edge id -> CSR slot
__device__ float g_inv[N_NODES];

__device__ __forceinline__ float siluf(float x) {
    return __fdividef(x, 1.0f + __expf(-x));
}
__device__ __forceinline__ uint32_t smem_u32(const void* p) {
    uint32_t a;
    asm("{ .reg .u64 t; cvta.to.shared.u64 t, %1; cvt.u32.u64 %0, t; }"
        : "=r"(a) : "l"(p));
    return a;
}
__device__ __forceinline__ uint32_t pk_bf2(float a, float b) {
    __nv_bfloat162 t = __floats2bfloat162_rn(a, b);
    return reinterpret_cast<uint32_t&>(t);
}
__device__ __forceinline__ float bf_hi(float v) {
    return __bfloat162float(__float2bfloat16(v));
}

#define LDSM4(r, a) \
    asm volatile("ldmatrix.sync.aligned.m8n8.x4.shared.b16 {%0,%1,%2,%3}, [%4];" \
        : "=r"((r)[0]), "=r"((r)[1]), "=r"((r)[2]), "=r"((r)[3]) : "r"(a))
#define LDSM4T(r, a) \
    asm volatile("ldmatrix.sync.aligned.m8n8.x4.trans.shared.b16 {%0,%1,%2,%3}, [%4];" \
        : "=r"((r)[0]), "=r"((r)[1]), "=r"((r)[2]), "=r"((r)[3]) : "r"(a))
#define MMA_BF16(c, a, b0, b1) \
    asm volatile( \
        "mma.sync.aligned.m16n8k16.row.col.f32.bf16.bf16.f32 " \
        "{%0,%1,%2,%3}, {%4,%5,%6,%7}, {%8,%9}, {%0,%1,%2,%3};" \
        : "+f"((c)[0]), "+f"((c)[1]), "+f"((c)[2]), "+f"((c)[3]) \
        : "r"((a)[0]), "r"((a)[1]), "r"((a)[2]), "r"((a)[3]), "r"(b0), "r"(b1))

// smem layout (bytes). 144B row stride -> conflict-free ldmatrix/STS.
#define STRA 144
#define WSTR 144
#define W_W2HI 0
#define W_W2LO 9216
#define W_C1HI 18432
#define W_C1LO 27648
#define SM_A 36864
#define A_WARP 4608        // per-warp: 16x144 hi + 16x144 lo
#define SM_B2 73728
#define SM_CB1 (SM_B2 + 256)
#define SM_COUT (SM_B2 + 512)
#define SM_W1C (SM_B2 + 768)
#define SMEM_EDGE_BYTES (SM_B2 + 1024)

// ---------------- setup kernels ----------------
__global__ void k_init(const float* __restrict__ inputs,
                       const float* __restrict__ emb_w,
                       const float* __restrict__ emb_b) {
    int idx = blockIdx.x * blockDim.x + threadIdx.x;
    if (idx >= N_NODES * HD) return;
    int n = idx >> 6, j = idx & 63;
    float vx = inputs[n * 6 + 3], vy = inputs[n * 6 + 4], vz = inputs[n * 6 + 5];
    float sp = sqrtf(vx * vx + vy * vy + vz * vz);
    g_h[idx] = sp * emb_w[j] + emb_b[j];
    if (j < 3) {
        g_coord[0][n * 3 + j] = inputs[n * 6 + j];
        g_vel[n * 3 + j] = inputs[n * 6 + 3 + j];
    }
    if (idx < N_NODES) g_cnt[idx] = 0;
}

__global__ void k_hist(const int* __restrict__ recv) {
    int e = blockIdx.x * blockDim.x + threadIdx.x;
    if (e < N_EDGES) atomicAdd(&g_cnt[recv[e]], 1);
}

__global__ void k_scan() {
    __shared__ int part[1024];
    const int CH = (N_NODES + 1023) / 1024;
    int t = threadIdx.x;
    int s = 0;
    for (int i = 0; i < CH; i++) {
        int idx = t * CH + i;
        if (idx < N_NODES) s += g_cnt[idx];
    }
    part[t] = s;
    __syncthreads();
    for (int d = 1; d < 1024; d <<= 1) {
        int v = (t >= d) ? part[t - d] : 0;
        __syncthreads();
        part[t] += v;
        __syncthreads();
    }
    int run = (t == 0) ? 0 : part[t - 1];
    for (int i = 0; i < CH; i++) {
        int idx = t * CH + i;
        if (idx < N_NODES) {
            g_off[idx] = run;
            g_cur[idx] = run;
            int c = g_cnt[idx];
            g_inv[idx] = 1.0f / fmaxf((float)c, 1.0f);
            run += c;
            if (idx == N_NODES - 1) g_off[N_NODES] = run;
        }
    }
}

__global__ void k_fill(const int* __restrict__ recv) {
    int e = blockIdx.x * blockDim.x + threadIdx.x;
    if (e >= N_EDGES) return;
    int p = atomicAdd(&g_cur[recv[e]], 1);
    g_pos[e] = p;
}

// ---------------- per-layer node precompute: A, B, P, v_gate ----------------
__global__ void __launch_bounds__(256) k_node_pre(
    const float* __restrict__ w1a, const float* __restrict__ w1b,
    const float* __restrict__ b1,
    const float* __restrict__ nw1a, const float* __restrict__ nb1,
    const float* __restrict__ vw1, const float* __restrict__ vb1,
    const float* __restrict__ vw2, const float* __restrict__ vb2) {
    __shared__ float sH[8][68];
    int warp = threadIdx.x >> 5, lane = threadIdx.x & 31;
    int n = blockIdx.x * 8 + warp;
    if (n >= N_NODES) return;
    sH[warp][lane] = g_h[n * 64 + lane];
    sH[warp][lane + 32] = g_h[n * 64 + lane + 32];
    __syncwarp();
    float aA = b1[lane], aA2 = b1[lane + 32];
    float aB = 0.f, aB2 = 0.f;
    float aP = nb1[lane], aP2 = nb1[lane + 32];
    float aV = vb1[lane], aV2 = vb1[lane + 32];
#pragma unroll 4
    for (int k = 0; k < 64; k++) {
        float hv = sH[warp][k];
        aA += hv * w1a[k * 64 + lane];    aA2 += hv * w1a[k * 64 + lane + 32];
        aB += hv * w1b[k * 64 + lane];    aB2 += hv * w1b[k * 64 + lane + 32];
        aP += hv * nw1a[k * 64 + lane];   aP2 += hv * nw1a[k * 64 + lane + 32];
        aV += hv * vw1[k * 64 + lane];    aV2 += hv * vw1[k * 64 + lane + 32];
    }
    g_A[n * 64 + lane] = aA; g_A[n * 64 + lane + 32] = aA2;
    g_B[n * 64 + lane] = aB; g_B[n * 64 + lane + 32] = aB2;
    g_P[n * 64 + lane] = aP; g_P[n * 64 + lane + 32] = aP2;
    float q = siluf(aV), q2 = siluf(aV2);
    float part = q * vw2[lane] + q2 * vw2[lane + 32];
#pragma unroll
    for (int o = 16; o; o >>= 1) part += __shfl_xor_sync(0xffffffffu, part, o);
    if (lane == 0) g_vg[n] = part + vb2[0];
}

// ---------------- edge kernel: mma.sync bf16 (triple split) ----------------
// Outputs (ef16, trans) are written at CSR slot g_pos[e] so the node kernel
// reads them fully streaming. p values are loaded only inside the epilogue
// blocks (never live across a GEMM body -> no spill pressure).
__global__ void __launch_bounds__(256, 3) k_edge(
    const int* __restrict__ send, const int* __restrict__ recv,
    const float* __restrict__ w2, const float* __restrict__ b2,
    const float* __restrict__ c1w, const float* __restrict__ cb1,
    const float* __restrict__ cout, const float* __restrict__ w1c,
    int parity, int writeEF) {
    extern __shared__ char sm8[];
    uint32_t sb = smem_u32(sm8);
    int tid = threadIdx.x, warp = tid >> 5, lane = tid & 31;

    // weights -> bf16 hi/lo in smem, row-major [k][n], 144B row stride
    for (int idx = tid; idx < 2048; idx += 256) {
        int k = idx >> 5, np = idx & 31;
        float a0 = w2[k * 64 + 2 * np], a1 = w2[k * 64 + 2 * np + 1];
        float c0 = c1w[k * 64 + 2 * np], c1v = c1w[k * 64 + 2 * np + 1];
        float a0h = bf_hi(a0), a1h = bf_hi(a1);
        float c0h = bf_hi(c0), c1h = bf_hi(c1v);
        uint32_t off = (uint32_t)(k * WSTR + np * 4);
        *(uint32_t*)(sm8 + W_W2HI + off) = pk_bf2(a0h, a1h);
        *(uint32_t*)(sm8 + W_W2LO + off) = pk_bf2(a0 - a0h, a1 - a1h);
        *(uint32_t*)(sm8 + W_C1HI + off) = pk_bf2(c0h, c1h);
        *(uint32_t*)(sm8 + W_C1LO + off) = pk_bf2(c0 - c0h, c1v - c1h);
    }
    float* sB2 = (float*)(sm8 + SM_B2);
    float* sCB1 = (float*)(sm8 + SM_CB1);
    float* sCOUT = (float*)(sm8 + SM_COUT);
    float* sW1C = (float*)(sm8 + SM_W1C);
    if (tid < 64) {
        sB2[tid] = b2[tid];
        sCB1[tid] = cb1[tid];
        sCOUT[tid] = cout[tid];
        sW1C[tid] = w1c[tid];
    }
    __syncthreads();

    const float* coord = g_coord[parity];
    char* aHiP = sm8 + SM_A + warp * A_WARP;
    char* aLoP = aHiP + 2304;
    uint32_t aHiB = sb + SM_A + warp * A_WARP;
    uint32_t aLoB = aHiB + 2304;

    // per-lane w1c pair (features 2*lane, 2*lane+1)
    float2 w1c2 = make_float2(sW1C[2 * lane], sW1C[2 * lane + 1]);

    // ldmatrix source addresses (per-thread)
    int m = lane >> 3, rr = lane & 7;
    uint32_t aRow = (uint32_t)(((m & 1) ? (8 + rr) : rr) * STRA + ((m >> 1) ? 16 : 0));
    uint32_t aAddrHi = aHiB + aRow;
    uint32_t aAddrLo = aLoB + aRow;
    // B: matrices 0,1 from HI (rows rr, 8+rr of the k-chunk); 2,3 from LO (+9216)
    uint32_t bOff = (uint32_t)((((m & 1) ? 8 : 0) + rr) * WSTR + ((m >> 1) ? 9216 : 0));
    uint32_t bG1 = sb + W_W2HI + bOff;
    uint32_t bG2 = sb + W_C1HI + bOff;

    const float2* b2v = (const float2*)sB2;
    const float2* cb1v = (const float2*)sCB1;
    const float2* coutv = (const float2*)sCOUT;

    int e16 = lane & 15;                 // this lane's edge (lanes 16-31 mirror)
    int r1 = lane >> 2, cq = lane & 3;   // C-frag mapping
    int r2 = r1 + 8;

    for (int t = blockIdx.x * 8 + warp; t < NTILE16; t += gridDim.x * 8) {
        int base = t * 16;
        int eMe = base + e16;
        int sI = send[eMe], rI = recv[eMe];
        float cdx = coord[sI * 3 + 0] - coord[rI * 3 + 0];
        float cdy = coord[sI * 3 + 1] - coord[rI * 3 + 1];
        float cdz = coord[sI * 3 + 2] - coord[rI * 3 + 2];
        float rad = cdx * cdx + cdy * cdy + cdz * cdz;

        // ---- ef1 = silu(A[s]+B[r]+rad*w1c): cooperative, row-coalesced ----
#pragma unroll 4
        for (int e = 0; e < 16; e++) {
            int s = __shfl_sync(0xffffffffu, sI, e);
            int r = __shfl_sync(0xffffffffu, rI, e);
            float rd = __shfl_sync(0xffffffffu, rad, e);
            float2 a = *(const float2*)(g_A + s * 64 + 2 * lane);
            float2 b = *(const float2*)(g_B + r * 64 + 2 * lane);
            float z0 = siluf(a.x + b.x + rd * w1c2.x);
            float z1 = siluf(a.y + b.y + rd * w1c2.y);
            float h0 = bf_hi(z0), h1 = bf_hi(z1);
            *(uint32_t*)(aHiP + e * STRA + lane * 4) = pk_bf2(h0, h1);
            *(uint32_t*)(aLoP + e * STRA + lane * 4) = pk_bf2(z0 - h0, z1 - h1);
        }
        __syncwarp();

        // ---- GEMM1: ef = silu(ef1 @ W2 + b2) ----
        float acc[8][4];
#pragma unroll
        for (int jt = 0; jt < 8; jt++) {
            acc[jt][0] = 0.f; acc[jt][1] = 0.f; acc[jt][2] = 0.f; acc[jt][3] = 0.f;
        }
#pragma unroll
        for (int kc = 0; kc < 4; kc++) {
            uint32_t ah[4], al[4];
            LDSM4(ah, aAddrHi + kc * 32);
            LDSM4(al, aAddrLo + kc * 32);
#pragma unroll
            for (int jt = 0; jt < 8; jt++) {
                uint32_t bb[4];
                LDSM4T(bb, bG1 + kc * 2304 + jt * 16);
                MMA_BF16(acc[jt], ah, bb[0], bb[1]);
                MMA_BF16(acc[jt], al, bb[0], bb[1]);
                MMA_BF16(acc[jt], ah, bb[2], bb[3]);
            }
        }
        __syncwarp();

        // ---- epilogue1: silu + bias; re-split into smem (conflict-free) ----
#pragma unroll
        for (int jt = 0; jt < 8; jt++) {
            float2 bb = b2v[jt * 4 + cq];
            float e0 = siluf(acc[jt][0] + bb.x), e1 = siluf(acc[jt][1] + bb.y);
            float e2 = siluf(acc[jt][2] + bb.x), e3 = siluf(acc[jt][3] + bb.y);
            int jc = jt * 8 + cq * 2;
            float h0 = bf_hi(e0), h1 = bf_hi(e1), h2 = bf_hi(e2), h3 = bf_hi(e3);
            *(uint32_t*)(aHiP + r1 * STRA + jc * 2) = pk_bf2(h0, h1);
            *(uint32_t*)(aHiP + r2 * STRA + jc * 2) = pk_bf2(h2, h3);
            *(uint32_t*)(aLoP + r1 * STRA + jc * 2) = pk_bf2(e0 - h0, e1 - h1);
            *(uint32_t*)(aLoP + r2 * STRA + jc * 2) = pk_bf2(e2 - h2, e3 - h3);
        }
        __syncwarp();

        // ---- g_ef16 writeback at CSR slot (one 128B line per edge) ----
        if (writeEF) {
            int pM = g_pos[base + e16];   // loaded here, dead after this block
#pragma unroll 4
            for (int e = 0; e < 16; e++) {
                int p = __shfl_sync(0xffffffffu, pM, e);
                uint32_t hp = *(const uint32_t*)(aHiP + e * STRA + lane * 4);
                uint32_t lp = *(const uint32_t*)(aLoP + e * STRA + lane * 4);
                __nv_bfloat162 hb = *reinterpret_cast<__nv_bfloat162*>(&hp);
                __nv_bfloat162 lb = *reinterpret_cast<__nv_bfloat162*>(&lp);
                float f0 = __bfloat162float(hb.x) + __bfloat162float(lb.x);
                float f1 = __bfloat162float(hb.y) + __bfloat162float(lb.y);
                *(__half2*)(g_ef16 + (size_t)p * 64 + 2 * lane) =
                    __floats2half2_rn(f0, f1);
            }
        }

        // ---- GEMM2: g = silu(ef @ C1 + cb1) ----
#pragma unroll
        for (int jt = 0; jt < 8; jt++) {
            acc[jt][0] = 0.f; acc[jt][1] = 0.f; acc[jt][2] = 0.f; acc[jt][3] = 0.f;
        }
#pragma unroll
        for (int kc = 0; kc < 4; kc++) {
            uint32_t ah[4], al[4];
            LDSM4(ah, aAddrHi + kc * 32);
            LDSM4(al, aAddrLo + kc * 32);
#pragma unroll
            for (int jt = 0; jt < 8; jt++) {
                uint32_t bb[4];
                LDSM4T(bb, bG2 + kc * 2304 + jt * 16);
                MMA_BF16(acc[jt], ah, bb[0], bb[1]);
                MMA_BF16(acc[jt], al, bb[0], bb[1]);
                MMA_BF16(acc[jt], ah, bb[2], bb[3]);
            }
        }

        // ---- epilogue2: cm = g . cout (quad reduce); trans at CSR slot ----
        float pr1 = 0.f, pr2 = 0.f;
#pragma unroll
        for (int jt = 0; jt < 8; jt++) {
            float2 cb = cb1v[jt * 4 + cq];
            float2 co = coutv[jt * 4 + cq];
            pr1 += siluf(acc[jt][0] + cb.x) * co.x + siluf(acc[jt][1] + cb.y) * co.y;
            pr2 += siluf(acc[jt][2] + cb.x) * co.x + siluf(acc[jt][3] + cb.y) * co.y;
        }
        pr1 += __shfl_xor_sync(0xffffffffu, pr1, 1);
        pr1 += __shfl_xor_sync(0xffffffffu, pr1, 2);
        pr2 += __shfl_xor_sync(0xffffffffu, pr2, 1);
        pr2 += __shfl_xor_sync(0xffffffffu, pr2, 2);
        float c1x = __shfl_sync(0xffffffffu, cdx, r1);
        float c1y = __shfl_sync(0xffffffffu, cdy, r1);
        float c1z = __shfl_sync(0xffffffffu, cdz, r1);
        float c2x = __shfl_sync(0xffffffffu, cdx, r2);
        float c2y = __shfl_sync(0xffffffffu, cdy, r2);
        float c2z = __shfl_sync(0xffffffffu, cdz, r2);
        if (cq == 0) {
            int p = g_pos[base + r1];
            g_trans[p * 3 + 0] = fminf(fmaxf(c1x * pr1, -100.f), 100.f);
            g_trans[p * 3 + 1] = fminf(fmaxf(c1y * pr1, -100.f), 100.f);
            g_trans[p * 3 + 2] = fminf(fmaxf(c1z * pr1, -100.f), 100.f);
        } else if (cq == 1) {
            int p = g_pos[base + r2];
            g_trans[p * 3 + 0] = fminf(fmaxf(c2x * pr2, -100.f), 100.f);
            g_trans[p * 3 + 1] = fminf(fmaxf(c2y * pr2, -100.f), 100.f);
            g_trans[p * 3 + 2] = fminf(fmaxf(c2z * pr2, -100.f), 100.f);
        }
        __syncwarp();
    }
}

// ---------------- per-layer node update (fully streaming gather) ----------------
__global__ void __launch_bounds__(256) k_node(
    const float* __restrict__ nw1b, const float* __restrict__ nw2,
    const float* __restrict__ nb2, int parity, int doH) {
    __shared__ float sA[8][68];
    int warp = threadIdx.x >> 5, lane = threadIdx.x & 31;
    int n = blockIdx.x * 8 + warp;
    if (n >= N_NODES) return;
    int start = g_off[n];
    int deg = g_off[n + 1] - start;
    float aH = 0.f, aH2 = 0.f, ax = 0.f, ay = 0.f, az = 0.f;
    for (int bchunk = 0; bchunk < deg; bchunk += 32) {
        int mm = deg - bchunk;
        if (mm > 32) mm = 32;
        int row = start + bchunk;
        if (lane < mm) {      // contiguous: 32 lanes cover 384B of g_trans
            const float* tp = g_trans + (size_t)(row + lane) * 3;
            ax += tp[0];
            ay += tp[1];
            az += tp[2];
        }
        if (doH) {            // streaming rows row..row+mm-1 (no indirection)
            const uint32_t* efb = (const uint32_t*)g_ef16 + (size_t)row * 32 + lane;
            int tt = 0;
            for (; tt + 4 <= mm; tt += 4) {
                uint32_t v0 = efb[0];
                uint32_t v1 = efb[32];
                uint32_t v2 = efb[64];
                uint32_t v3 = efb[96];
                efb += 128;
                float2 f0 = __half22float2(*reinterpret_cast<__half2*>(&v0));
                float2 f1 = __half22float2(*reinterpret_cast<__half2*>(&v1));
                float2 f2 = __half22float2(*reinterpret_cast<__half2*>(&v2));
                float2 f3 = __half22float2(*reinterpret_cast<__half2*>(&v3));
                aH += (f0.x + f1.x) + (f2.x + f3.x);
                aH2 += (f0.y + f1.y) + (f2.y + f3.y);
            }
            for (; tt < mm; tt++) {
                uint32_t v = efb[0];
                efb += 32;
                float2 f = __half22float2(*reinterpret_cast<__half2*>(&v));
                aH += f.x;
                aH2 += f.y;
            }
        }
    }
#pragma unroll
    for (int o = 16; o; o >>= 1) {
        ax += __shfl_xor_sync(0xffffffffu, ax, o);
        ay += __shfl_xor_sync(0xffffffffu, ay, o);
        az += __shfl_xor_sync(0xffffffffu, az, o);
    }
    if (doH) {
        // lane holds agg for features 2*lane, 2*lane+1
        sA[warp][2 * lane] = aH;
        sA[warp][2 * lane + 1] = aH2;
        __syncwarp();
        float aQ = g_P[n * 64 + lane], aQ2 = g_P[n * 64 + lane + 32];
#pragma unroll 4
        for (int k = 0; k < 64; k++) {
            float v = sA[warp][k];
            aQ += v * nw1b[k * 64 + lane];
            aQ2 += v * nw1b[k * 64 + lane + 32];
        }
        float t1 = siluf(aQ), t2 = siluf(aQ2);
        __syncwarp();
        sA[warp][lane] = t1;
        sA[warp][lane + 32] = t2;
        __syncwarp();
        float aO = nb2[lane] + g_h[n * 64 + lane];
        float aO2 = nb2[lane + 32] + g_h[n * 64 + lane + 32];
#pragma unroll 4
        for (int k = 0; k < 64; k++) {
            float v = sA[warp][k];
            aO += v * nw2[k * 64 + lane];
            aO2 += v * nw2[k * 64 + lane + 32];
        }
        g_h[n * 64 + lane] = aO;
        g_h[n * 64 + lane + 32] = aO2;
    }
    if (lane < 3) {
        float iv = g_inv[n];
        float agg = (lane == 0) ? ax : ((lane == 1) ? ay : az);
        float vo = g_vel[n * 3 + lane];
        float vn = agg * iv + g_vg[n] * vo;
        g_vel[n * 3 + lane] = vn;
        g_coord[parity ^ 1][n * 3 + lane] = g_coord[parity][n * 3 + lane] + vn;
    }
}

__global__ void k_out(float* __restrict__ out) {
    int idx = blockIdx.x * blockDim.x + threadIdx.x;
    if (idx >= N_NODES * 3) return;
    int n = idx / 3, c = idx % 3;
    out[n * 6 + c] = g_coord[0][idx];
    out[n * 6 + 3 + c] = g_vel[idx];
}

// ---------------- host launcher ----------------
extern "C" void kernel_launch(void* const* d_in, const int* in_sizes, int n_in,
                              void* d_out, int out_size) {
    const float* inputs = (const float*)d_in[0];
    const int* send = (const int*)d_in[2];
    const int* recv = (const int*)d_in[3];
    const float* emb_w = (const float*)d_in[4];
    const float* emb_b = (const float*)d_in[5];
    const float* ew1 = (const float*)d_in[6];   // (L,129,64)
    const float* eb1 = (const float*)d_in[7];
    const float* ew2 = (const float*)d_in[8];   // (L,64,64)
    const float* eb2 = (const float*)d_in[9];
    const float* nw1 = (const float*)d_in[10];  // (L,128,64)
    const float* nb1 = (const float*)d_in[11];
    const float* nw2 = (const float*)d_in[12];
    const float* nb2 = (const float*)d_in[13];
    const float* cw1 = (const float*)d_in[14];
    const float* cb1 = (const float*)d_in[15];
    const float* cwo = (const float*)d_in[16];
    const float* vw1 = (const float*)d_in[17];
    const float* vb1 = (const float*)d_in[18];
    const float* vw2 = (const float*)d_in[19];
    const float* vb2 = (const float*)d_in[20];
    float* out = (float*)d_out;

    cudaFuncSetAttribute(k_edge, cudaFuncAttributeMaxDynamicSharedMemorySize,
                         SMEM_EDGE_BYTES);

    k_init<<<(N_NODES * HD + 255) / 256, 256>>>(inputs, emb_w, emb_b);
    k_hist<<<(N_EDGES + 511) / 512, 512>>>(recv);
    k_scan<<<1, 1024>>>();
    k_fill<<<(N_EDGES + 511) / 512, 512>>>(recv);

    for (int l = 0; l < NLAYERS; l++) {
        int par = l & 1;
        int last = (l == NLAYERS - 1);
        k_node_pre<<<(N_NODES + 7) / 8, 256>>>(
            ew1 + l * 8256, ew1 + l * 8256 + 4096, eb1 + l * 64,
            nw1 + l * 8192, nb1 + l * 64,
            vw1 + l * 4096, vb1 + l * 64, vw2 + l * 64, vb2 + l);
        k_edge<<<444, 256, SMEM_EDGE_BYTES>>>(
            send, recv, ew2 + l * 4096, eb2 + l * 64,
            cw1 + l * 4096, cb1 + l * 64, cwo + l * 64,
            ew1 + l * 8256 + 8192, par, last ? 0 : 1);
        k_node<<<(N_NODES + 7) / 8, 256>>>(
            nw1 + l * 8192 + 4096, nw2 + l * 4096, nb2 + l * 64, par,
            last ? 0 : 1);
    }
    k_out<<<(N_NODES * 3 + 255) / 256, 256>>>(out);
}